// round 17
// baseline (speedup 1.0000x reference)
#include <cuda_runtime.h>
#include <cuda_fp16.h>
#include <math.h>
#include <stdint.h>

// ---------------- constants ----------------
#define HW 64
#define NF 64
#define BB 32
#define TT 12
#define PHW 66
#define PPX (PHW*PHW)                 // 4356
#define STATE_ELEMS (BB*NF*HW*HW)     // 8,388,608
#define Y_ELEMS (BB*TT*HW*HW)         // 1,572,864

// ---------------- smem layout (bytes) ----------------
#define O_INH 0                       // input slab: 264 px * 144B (4 rows x 66)
#define O_WB  38016                   // 4 weight bufs: 256 oc * 144B each
#define WBSZ  36864
#define O_XI  185472                  // x im2col: per-warp 32 px * 48B (16 regions)
#define O_WXH 210048                  // Wx fp16: 256 oc * 48B
#define O_XS  222336                  // x halo slab: 264 fp32
#define O_HW  223392                  // head weights: 576 fp32
#define SMEM_BYTES 225792

// ---------------- device globals ----------------
__device__ float g_c[STATE_ELEMS];
__device__ __align__(16) __half g_nhA_hi[BB*PPX*NF];
__device__ __align__(16) __half g_nhB_hi[BB*PPX*NF];
__device__ __align__(16) __half g_WhE[9*256*64];   // [tap][oc][ch] fp16
__device__ __align__(16) __half g_WdX[9*256*64];
__device__ __align__(16) __half g_WdS[9*256*64];
__device__ __align__(16) __half g_Wx16[256*16];    // [oc][16] (9 taps + pad)

// ---------------- PTX helpers ----------------
__device__ __forceinline__ uint32_t smem_u32(const void* p) {
    uint32_t a;
    asm("{ .reg .u64 t; cvta.to.shared.u64 t, %1; cvt.u32.u64 %0, t; }" : "=r"(a) : "l"(p));
    return a;
}
__device__ __forceinline__ void cp16_s(uint32_t sdst, const void* g) {
    asm volatile("cp.async.cg.shared.global [%0], [%1], 16;" :: "r"(sdst), "l"(g));
}
__device__ __forceinline__ void ldsm4(uint32_t* r, uint32_t addr) {
    asm volatile("ldmatrix.sync.aligned.m8n8.x4.shared.b16 {%0,%1,%2,%3}, [%4];"
        : "=r"(r[0]), "=r"(r[1]), "=r"(r[2]), "=r"(r[3]) : "r"(addr));
}
__device__ __forceinline__ void mma16816(float* d, const uint32_t* a, const uint32_t* b) {
    asm volatile("mma.sync.aligned.m16n8k16.row.col.f32.f16.f16.f32 "
        "{%0,%1,%2,%3}, {%4,%5,%6,%7}, {%8,%9}, {%0,%1,%2,%3};"
        : "+f"(d[0]), "+f"(d[1]), "+f"(d[2]), "+f"(d[3])
        : "r"(a[0]), "r"(a[1]), "r"(a[2]), "r"(a[3]), "r"(b[0]), "r"(b[1]));
}
__device__ __forceinline__ float sigmoidf_(float x) { return 1.f / (1.f + __expf(-x)); }
__device__ __forceinline__ float tanhf_(float x) {
    float e = __expf(2.f * x);
    return (e - 1.f) * __frcp_rn(e + 1.f);
}

// ---------------- prep kernels ----------------
__global__ void zero_buf(float* __restrict__ p, int n) {
    for (int i = blockIdx.x * blockDim.x + threadIdx.x; i < n; i += gridDim.x * blockDim.x)
        p[i] = 0.f;
}
// W[oc][CIN][9] -> dst[tap][oc][64ch] fp16, channels off1.., optional fold +off2
__global__ void prep_wh(const float* __restrict__ W, __half* __restrict__ dst,
                        int CIN, int off1, int off2) {
    int idx = blockIdx.x * blockDim.x + threadIdx.x;
    if (idx >= 9 * 256 * 64) return;
    int ch = idx & 63, oc = (idx >> 6) & 255, tap = idx >> 14;
    float w = W[((size_t)oc * CIN + off1 + ch) * 9 + tap];
    if (off2 >= 0) w += W[((size_t)oc * CIN + off2 + ch) * 9 + tap];
    dst[((size_t)tap * 256 + oc) * 64 + ch] = __float2half(w);
}
__global__ void prep_wx16(const float* __restrict__ W, __half* __restrict__ dst) {
    int idx = blockIdx.x * blockDim.x + threadIdx.x;
    if (idx >= 4096) return;
    int oc = idx >> 4, k = idx & 15;
    float v = (k < 9) ? W[((size_t)oc * 65) * 9 + k] : 0.f;   // cin 0 = x
    dst[idx] = __float2half(v);
}

// ---------------- ConvLSTM step: fp16 mma.sync implicit GEMM ----------------
// grid 1024 = 32 b x 32 y-pairs (2 rows); 512 threads (16 warps: 4 chblk x 4 N)
// A rows: gate = mf*64, ch-block = mw*16 -> in-register i/f/o/g epilogue.
// x path: warp-local im2col + one K=16 MMA pass inside chunk 0's barrier.
__global__ void __launch_bounds__(512, 1)
conv_step(const __half* __restrict__ hi_in,
          __half* __restrict__ hi_out,
          float* __restrict__ c,
          const __half* __restrict__ Wm,
          const float* __restrict__ x, int t,
          const float* __restrict__ bias, int has_mma, int has_x,
          int do_head, int tout,
          const float* __restrict__ Wc, const float* __restrict__ bc,
          float* __restrict__ yout,
          int do_ev, float* __restrict__ evout) {
    extern __shared__ __align__(16) unsigned char smem[];
    const uint32_t sb = smem_u32(smem);
    const int tid = threadIdx.x, wid = tid >> 5, lane = tid & 31;
    const int b = blockIdx.x >> 5, yg = blockIdx.x & 31, y0 = yg * 2;

    auto stage_w = [&](int ci) {
        uint32_t dstoff = O_WB + (uint32_t)(ci & 3) * WBSZ;
        const char* src = (const char*)(Wm + (size_t)ci * 16384);
#pragma unroll
        for (int j = 0; j < 4; j++) {
            int idx = tid + j * 512;            // 0..2047
            int oc = idx >> 3, seg = idx & 7;
            cp16_s(sb + dstoff + oc * 144 + seg * 16, src + oc * 128 + seg * 16);
        }
        asm volatile("cp.async.commit_group;" ::: "memory");
    };

    // ---- async staging: slab + 4 weight chunks ----
    if (has_mma) {
        const char* hbase = (const char*)(hi_in + ((size_t)b * PPX + (size_t)y0 * PHW) * 64);
#pragma unroll
        for (int j = 0; j < 5; j++) {
            int idx = tid + j * 512;
            if (idx < 2112) {                    // 264 px * 8 segs
                int p = idx >> 3, seg = idx & 7;
                cp16_s(sb + O_INH + p * 144 + seg * 16, hbase + p * 128 + seg * 16);
            }
        }
        // group0 = slab + chunk0
        {
            const char* src = (const char*)Wm;
#pragma unroll
            for (int j = 0; j < 4; j++) {
                int idx = tid + j * 512;
                int oc = idx >> 3, seg = idx & 7;
                cp16_s(sb + O_WB + oc * 144 + seg * 16, src + oc * 128 + seg * 16);
            }
            asm volatile("cp.async.commit_group;" ::: "memory");
        }
        stage_w(1);
        stage_w(2);
        stage_w(3);
    }

    // ---- plain-load staging (overlaps with cp.async latency) ----
    if (has_x) {
        if (tid < 264) {
            int r = tid / 66, cc = tid % 66;
            int gy = y0 + r - 1, gx = cc - 1;
            float v = 0.f;
            if ((unsigned)gy < 64u && (unsigned)gx < 64u)
                v = x[((size_t)b * TT + t) * 4096 + gy * 64 + gx];
            ((float*)(smem + O_XS))[tid] = v;
        }
#pragma unroll
        for (int j = 0; j < 8; j++) {
            int idx = tid + j * 512;            // 0..4095
            int oc = idx >> 4, k = idx & 15;
            *(__half*)(smem + O_WXH + oc * 48 + k * 2) = g_Wx16[idx];
        }
    }
    if (do_head) {
        for (int i = tid; i < 576; i += 512) {
            int tap = i >> 6, ch = i & 63;
            ((float*)(smem + O_HW))[i] = Wc[ch * 9 + tap];
        }
    }

    // ---- fragment geometry ----
    const int mw = wid & 3;                  // 16-ch block within each gate
    const int nw = wid >> 2;                 // px quarter (32 px)
    const uint32_t a_kh = ((lane >> 4) << 3);
    const int nfsel = lane >> 4;
    const int khalf = (lane >> 3) & 1;
    const int grp = lane >> 2, tig = lane & 3;
    int prow[4], pcol[4];
#pragma unroll
    for (int nf = 0; nf < 4; nf++) {
        int p = nw * 32 + nf * 8 + (lane & 7);
        prow[nf] = p >> 6;
        pcol[nf] = p & 63;
    }

    float acc[4][4][4];                      // [gate][nf][dreg]
#pragma unroll
    for (int i = 0; i < 4; i++)
#pragma unroll
        for (int j = 0; j < 4; j++)
#pragma unroll
            for (int k = 0; k < 4; k++) acc[i][j][k] = 0.f;

    float cold[16];

    auto load_cold = [&]() {
#pragma unroll
        for (int half = 0; half < 2; half++) {
            const int ch = mw * 16 + grp + half * 8;
#pragma unroll
            for (int nf = 0; nf < 4; nf++)
#pragma unroll
                for (int kk = 0; kk < 2; kk++) {
                    int px = nw * 32 + nf * 8 + tig * 2 + kk;
                    cold[half * 8 + nf * 2 + kk] =
                        c[(((size_t)b * 64 + y0 + (px >> 6)) * 64 + (px & 63)) * 64 + ch];
                }
        }
    };

    // warp-local x path: build im2col (own 32 px), syncwarp, one K=16 MMA pass
    auto x_pass = [&]() {
        const uint32_t xi = sb + O_XI + (uint32_t)wid * 1536;
        const float* sxp = (const float*)(smem + O_XS);
#pragma unroll
        for (int i = 0; i < 16; i++) {
            int idx = lane + i * 32;          // 0..511
            int pl = idx >> 4, k = idx & 15;
            int px = nw * 32 + pl;
            float v = 0.f;
            if (k < 9)
                v = sxp[((px >> 6) + k / 3) * 66 + (k % 3) + (px & 63)];
            *(__half*)(smem + O_XI + wid * 1536 + pl * 48 + k * 2) = __float2half(v);
        }
        __syncwarp();
        uint32_t afx[4][4];
#pragma unroll
        for (int mf = 0; mf < 4; mf++) {
            uint32_t arow = (uint32_t)(mf * 64 + mw * 16 + (lane & 15));
            ldsm4(afx[mf], sb + O_WXH + arow * 48 + a_kh * 2);
        }
        uint32_t bfx[2][4];
#pragma unroll
        for (int j = 0; j < 2; j++) {
            uint32_t pl = (uint32_t)((j * 2 + nfsel) * 8 + (lane & 7));
            ldsm4(bfx[j], xi + pl * 48 + khalf * 16);
        }
#pragma unroll
        for (int mf = 0; mf < 4; mf++)
#pragma unroll
            for (int nf = 0; nf < 4; nf++)
                mma16816(acc[mf][nf], afx[mf], &bfx[nf >> 1][(nf & 1) * 2]);
    };

    if (has_mma) {
        // ---- h-chunk loop (9 taps), 4-deep weight pipeline ----
        for (int ci = 0; ci < 9; ci++) {
            int wg = 8 - ci; if (wg > 3) wg = 3;
            switch (wg) {
                case 3: asm volatile("cp.async.wait_group 3;" ::: "memory"); break;
                case 2: asm volatile("cp.async.wait_group 2;" ::: "memory"); break;
                case 1: asm volatile("cp.async.wait_group 1;" ::: "memory"); break;
                default: asm volatile("cp.async.wait_group 0;" ::: "memory"); break;
            }
            __syncthreads();

            if (ci == 0) {
                if (has_x) x_pass();
                // fused CNN head: spread over all 16 warps, 4 lanes per px
                if (do_head) {
                    const int px = wid * 8 + (lane >> 2);
                    const int cb = (lane & 3) * 16;
                    const int pr = px >> 6, pc = px & 63;
                    float part = 0.f;
#pragma unroll
                    for (int ky = 0; ky < 3; ky++)
#pragma unroll
                        for (int kx = 0; kx < 3; kx++) {
                            const uint32_t base =
                                (uint32_t)(((pr + ky) * 66 + pc + kx) * 144);
                            const float* wr =
                                (const float*)(smem + O_HW) + (ky * 3 + kx) * 64 + cb;
#pragma unroll
                            for (int ch = 0; ch < 16; ch += 2) {
                                uint32_t hp = *(const uint32_t*)(smem + O_INH + base +
                                                                 (cb + ch) * 2);
                                float2 hf = __half22float2(*(__half2*)&hp);
                                part += wr[ch] * hf.x + wr[ch + 1] * hf.y;
                            }
                        }
                    part += __shfl_xor_sync(0xffffffffu, part, 1);
                    part += __shfl_xor_sync(0xffffffffu, part, 2);
                    if ((lane & 3) == 0)
                        yout[((size_t)b * TT + tout) * 4096 + (y0 + pr) * 64 + pc] =
                            part + __ldg(bc);
                }
                // fused encoder-vector output (decoder t=0)
                if (do_ev) {
                    const int xx = tid & 63;
                    const int pr = (tid >> 6) & 1;
                    const int chb = (tid >> 7) * 16;
                    const uint32_t base = (uint32_t)(((pr + 1) * 66 + xx + 1) * 144);
#pragma unroll
                    for (int j = 0; j < 16; j++) {
                        int ch = chb + j;
                        __half hv = *(const __half*)(smem + O_INH + base + ch * 2);
                        evout[((size_t)b * 64 + ch) * 4096 + (y0 + pr) * 64 + xx] =
                            __half2float(hv);
                    }
                }
            }
            if (ci == 8) load_cold();           // hidden under last chunk's MMAs

            if (ci + 3 < 9) stage_w(ci + 3);

            const uint32_t wb = sb + O_WB + (uint32_t)(ci & 3) * WBSZ;
            const int dy = ci / 3, dx = ci % 3;
            uint32_t bco[2];
#pragma unroll
            for (int j = 0; j < 2; j++) {
                int nf = j * 2 + nfsel;
                bco[j] = (uint32_t)(((prow[nf] + dy) * 66 + pcol[nf] + dx) * 144 + khalf * 16);
            }

#pragma unroll
            for (int ks = 0; ks < 4; ks++) {
                const int k0 = ks * 16;
                uint32_t af[4][4];
#pragma unroll
                for (int mf = 0; mf < 4; mf++) {
                    uint32_t arow = (uint32_t)(mf * 64 + mw * 16 + (lane & 15));
                    ldsm4(af[mf], wb + arow * 144 + (k0 + a_kh) * 2);
                }
                uint32_t bf4[2][4];
                ldsm4(bf4[0], sb + O_INH + bco[0] + k0 * 2);
                ldsm4(bf4[1], sb + O_INH + bco[1] + k0 * 2);
#pragma unroll
                for (int mf = 0; mf < 4; mf++)
#pragma unroll
                    for (int nf = 0; nf < 4; nf++)
                        mma16816(acc[mf][nf], af[mf], &bf4[nf >> 1][(nf & 1) * 2]);
            }
        }
    } else {
        // encoder t=0: x only
        __syncthreads();                       // xs + WXH visible
        if (has_x) x_pass();
        load_cold();
    }

    // ---- in-register LSTM pointwise epilogue ----
#pragma unroll
    for (int half = 0; half < 2; half++) {
        const int ch = mw * 16 + grp + half * 8;
        const float bi  = __ldg(bias + ch);
        const float bf_ = __ldg(bias + 64 + ch);
        const float bo  = __ldg(bias + 128 + ch);
        const float bg  = __ldg(bias + 192 + ch);

#pragma unroll
        for (int nf = 0; nf < 4; nf++)
#pragma unroll
            for (int kk = 0; kk < 2; kk++) {
                const int k = half * 2 + kk;
                const int px = nw * 32 + nf * 8 + tig * 2 + kk;
                const int pr = px >> 6, pc = px & 63;
                float vi = acc[0][nf][k] + bi;
                float vf = acc[1][nf][k] + bf_;
                float vo = acc[2][nf][k] + bo;
                float vg = acc[3][nf][k] + bg;
                const int y = y0 + pr;
                const size_t coff = (((size_t)b * 64 + y) * 64 + pc) * 64 + ch;
                float cn = sigmoidf_(vf) * cold[half * 8 + nf * 2 + kk]
                         + sigmoidf_(vi) * tanhf_(vg);
                c[coff] = cn;
                float hv = sigmoidf_(vo) * tanhf_(cn);
                const size_t hoff =
                    ((size_t)b * PPX + (size_t)(y + 1) * PHW + (pc + 1)) * 64 + ch;
                hi_out[hoff] = __float2half(hv);
            }
    }
}

// ---------------- standalone 3D CNN head (final decoder step only) ----------------
__global__ void cnn_head(const __half* __restrict__ hi,
                         const float* __restrict__ Wc, const float* __restrict__ bc,
                         float* __restrict__ out, int t) {
    __shared__ float s_w[9 * 64];
    int b = blockIdx.x >> 4, yg = blockIdx.x & 15, y0 = yg * 4;
    int tid = threadIdx.x;
    for (int i = tid; i < 576; i += 256) {
        int ch = i / 9, tap = i % 9;
        s_w[tap * 64 + ch] = Wc[i];
    }
    __syncthreads();
    int r = tid >> 6, xx = tid & 63, iy = y0 + r;
    float acc = bc[0];
#pragma unroll
    for (int ky = 0; ky < 3; ky++)
#pragma unroll
        for (int kx = 0; kx < 3; kx++) {
            size_t base = (((size_t)b * PPX) + (size_t)(iy + ky) * PHW + (xx + kx)) * 64;
            const float* wrow = s_w + (ky * 3 + kx) * 64;
            float s = 0.f;
            for (int ch = 0; ch < 64; ch++)
                s += wrow[ch] * __half2float(hi[base + ch]);
            acc += s;
        }
    out[((size_t)b * TT + t) * 4096 + iy * 64 + xx] = acc;
}

// ---------------- launch ----------------
extern "C" void kernel_launch(void* const* d_in, const int* in_sizes, int n_in,
                              void* d_out, int out_size) {
    const float* x     = (const float*)d_in[0];
    const float* W_enc = (const float*)d_in[2];
    const float* b_enc = (const float*)d_in[3];
    const float* W_dec = (const float*)d_in[4];
    const float* b_dec = (const float*)d_in[5];
    const float* W_cnn = (const float*)d_in[6];
    const float* b_cnn = (const float*)d_in[7];
    float* out = (float*)d_out;

    float* c;
    __half *ahi, *bhi, *whe, *wdx, *wds, *wx16;
    cudaGetSymbolAddress((void**)&c, g_c);
    cudaGetSymbolAddress((void**)&ahi, g_nhA_hi);
    cudaGetSymbolAddress((void**)&bhi, g_nhB_hi);
    cudaGetSymbolAddress((void**)&whe, g_WhE);
    cudaGetSymbolAddress((void**)&wdx, g_WdX);
    cudaGetSymbolAddress((void**)&wds, g_WdS);
    cudaGetSymbolAddress((void**)&wx16, g_Wx16);

    cudaFuncSetAttribute(conv_step, cudaFuncAttributeMaxDynamicSharedMemorySize, SMEM_BYTES);

    zero_buf<<<2048, 256>>>(c, STATE_ELEMS);
    zero_buf<<<2048, 256>>>((float*)ahi, BB * PPX * NF / 2);
    zero_buf<<<2048, 256>>>((float*)bhi, BB * PPX * NF / 2);

    prep_wh<<<576, 256>>>(W_enc, whe, 65, 1, -1);
    prep_wh<<<576, 256>>>(W_dec, wdx, 128, 0, -1);
    prep_wh<<<576, 256>>>(W_dec, wds, 128, 0, 64);
    prep_wx16<<<16, 256>>>(W_enc, wx16);

    __half *curhi = ahi, *othhi = bhi;

    // ---- encoder ----
    for (int t = 0; t < TT; t++) {
        conv_step<<<1024, 512, SMEM_BYTES>>>(curhi, othhi, c,
                                             whe, x, t, b_enc, t > 0, 1,
                                             0, 0, W_cnn, b_cnn, out, 0, out);
        __half* tp = curhi; curhi = othhi; othhi = tp;
    }

    // decoder state restarts at zero (c only)
    zero_buf<<<2048, 256>>>(c, STATE_ELEMS);

    // ---- decoder (head for t-1 and ev output fused into prologues) ----
    for (int t = 0; t < TT; t++) {
        const __half* W = (t == 0) ? wdx : wds;
        conv_step<<<1024, 512, SMEM_BYTES>>>(curhi, othhi, c,
                                             W, x, t, b_dec, 1, 0,
                                             t > 0, t - 1, W_cnn, b_cnn, out,
                                             t == 0, out + Y_ELEMS);
        __half* tp = curhi; curhi = othhi; othhi = tp;
    }
    // final head for t = 11 from the last h
    cnn_head<<<512, 256>>>(curhi, W_cnn, b_cnn, out, TT - 1);
}